// round 7
// baseline (speedup 1.0000x reference)
#include <cuda_runtime.h>
#include <cuda_bf16.h>
#include <cstdint>

#define Ss   2048
#define Hh   2048
#define BS   4096
#define NZ   32          // B * NUM_HEADS
#define HDim 128

typedef __nv_bfloat16 bf16;

// ---------------- fp32 scratch ----------------
__device__ float g_Sc[134217728];     // scores (fp32)
__device__ float g_M[65536];          // per-row masked max
__device__ float g_L[65536];          // per-row sum of exp

// ---------------- bf16 hi/lo scratch ----------------
__device__ bf16 g_tAh[12582912], g_tAl[12582912];   // 3x W?m^T (slice 4M); slice0 reused for Wo^T
__device__ bf16 g_tBh[12582912], g_tBl[12582912];   // 3x Wq/Wk/Wv
__device__ bf16 g_WcTh[12582912], g_WcTl[12582912]; // 3x combined weight^T
__device__ bf16 g_Xh[8388608],  g_Xl[8388608];
__device__ bf16 g_Pjh[25165824], g_Pjl[25165824];   // Q|K|V projections split (3 x 8M)
__device__ bf16 g_Vth[8388608], g_Vtl[8388608];     // per-head V^T: [32][128][2048]
__device__ bf16 g_Atth[8388608], g_Attl[8388608];

// ---------------------------------------------------------------------------
// helpers
// ---------------------------------------------------------------------------
__device__ __forceinline__ void ldsm4(uint32_t a, uint32_t &r0, uint32_t &r1,
                                      uint32_t &r2, uint32_t &r3) {
    asm volatile("ldmatrix.sync.aligned.m8n8.x4.shared.b16 {%0,%1,%2,%3}, [%4];"
                 : "=r"(r0), "=r"(r1), "=r"(r2), "=r"(r3) : "r"(a));
}
__device__ __forceinline__ void mma16816(float c[4], uint32_t a0, uint32_t a1,
                                         uint32_t a2, uint32_t a3,
                                         uint32_t b0, uint32_t b1) {
    asm volatile("mma.sync.aligned.m16n8k16.row.col.f32.bf16.bf16.f32 "
                 "{%0,%1,%2,%3}, {%4,%5,%6,%7}, {%8,%9}, {%0,%1,%2,%3};"
                 : "+f"(c[0]), "+f"(c[1]), "+f"(c[2]), "+f"(c[3])
                 : "r"(a0), "r"(a1), "r"(a2), "r"(a3), "r"(b0), "r"(b1));
}
__device__ __forceinline__ void cpa16(uint32_t s, const void* g) {
    asm volatile("cp.async.cg.shared.global [%0], [%1], 16;" :: "r"(s), "l"(g));
}
__device__ __forceinline__ void split2(float x, bf16 &h, bf16 &l) {
    h = __float2bfloat16(x);
    l = __float2bfloat16(x - __bfloat162float(h));
}

// ---------------------------------------------------------------------------
// bf16x3 NT GEMM: C[M][N] = (Ah+Al)[M][K] @ (Bh+Bl)[N][K]^T (fp32 accum)
// 128x128 CTA tile, BK=32, 128 threads (4 warps, 2x2), warp tile 64x64.
// 3-stage cp.async ring. OUT=0: fp32 C.  OUT=1: bf16 hi/lo pair.
// ---------------------------------------------------------------------------
template <int OUT>
__global__ void __launch_bounds__(128)
mma_nt(const bf16* __restrict__ Ah, const bf16* __restrict__ Al,
       const bf16* __restrict__ Bh, const bf16* __restrict__ Bl,
       float* __restrict__ C, bf16* __restrict__ Ch, bf16* __restrict__ Cl,
       int K, int lda, int ldb, int ldc,
       long sA, long sB, long sC)
{
    extern __shared__ char smem[];
    const uint32_t sbase = (uint32_t)__cvta_generic_to_shared(smem);

    const int z = blockIdx.z;
    Ah += (long)z * sA;  Al += (long)z * sA;
    Bh += (long)z * sB;  Bl += (long)z * sB;

    const int m0 = blockIdx.y * 128;
    const int n0 = blockIdx.x * 128;
    const int tid  = threadIdx.x;
    const int lane = tid & 31;
    const int w    = tid >> 5;
    const int wm   = (w & 2) * 32;
    const int wn   = (w & 1) * 64;

    const int la15 = lane & 15;
    const int lac  = lane >> 4;
    const int lb   = ((lane >> 4) << 3) + (lane & 7);
    const int lbg  = (lane >> 3) & 1;

    int offA[4], swA[4];
#pragma unroll
    for (int i = 0; i < 4; i++) {
        int r = wm + i * 16 + la15;
        offA[i] = r * 64;  swA[i] = (r >> 1) & 3;
    }
    int offB[4], swB[4];
#pragma unroll
    for (int p = 0; p < 4; p++) {
        int r = wn + p * 16 + lb;
        offB[p] = r * 64;  swB[p] = (r >> 1) & 3;
    }

    float acc[4][8][4];
#pragma unroll
    for (int i = 0; i < 4; i++)
#pragma unroll
        for (int j = 0; j < 8; j++)
#pragma unroll
            for (int r = 0; r < 4; r++) acc[i][j][r] = 0.0f;

    auto load_stage = [&](int t, int st) {
        const uint32_t sb = sbase + st * 32768;
        const int k0 = t * 32;
#pragma unroll
        for (int i = 0; i < 16; i++) {
            const int q = i * 128 + tid;
            const int tile = q >> 9;
            const int idx = q & 511;
            const int row = idx >> 2, c = idx & 3;
            const uint32_t sw = row * 64 + ((c ^ ((row >> 1) & 3)) << 4);
            const bf16* g;
            if (tile == 0)      g = Ah + (long)(m0 + row) * lda + k0 + c * 8;
            else if (tile == 1) g = Al + (long)(m0 + row) * lda + k0 + c * 8;
            else if (tile == 2) g = Bh + (long)(n0 + row) * ldb + k0 + c * 8;
            else                g = Bl + (long)(n0 + row) * ldb + k0 + c * 8;
            cpa16(sb + tile * 8192 + sw, g);
        }
        asm volatile("cp.async.commit_group;" ::: "memory");
    };

    const int T = K >> 5;
    load_stage(0, 0);
    load_stage(1, 1);

    int st = 0;
    for (int t = 0; t < T; t++) {
        if (t < T - 1) asm volatile("cp.async.wait_group 1;" ::: "memory");
        else           asm volatile("cp.async.wait_group 0;" ::: "memory");
        __syncthreads();
        if (t + 2 < T) {
            int ns = st + 2; if (ns >= 3) ns -= 3;
            load_stage(t + 2, ns);
        }

        const uint32_t sb = sbase + st * 32768;
#pragma unroll
        for (int kk = 0; kk < 2; kk++) {
            uint32_t bh[16], bl[16], a[16];
#pragma unroll
            for (int p = 0; p < 4; p++) {
                const uint32_t ca = (uint32_t)(((kk * 2) + lbg) ^ swB[p]) << 4;
                ldsm4(sb + 16384 + offB[p] + ca, bh[p*4], bh[p*4+1], bh[p*4+2], bh[p*4+3]);
                ldsm4(sb + 24576 + offB[p] + ca, bl[p*4], bl[p*4+1], bl[p*4+2], bl[p*4+3]);
            }
#pragma unroll
            for (int i = 0; i < 4; i++) {
                const uint32_t ca = (uint32_t)(((kk * 2) + lac) ^ swA[i]) << 4;
                ldsm4(sb + offA[i] + ca, a[i*4], a[i*4+1], a[i*4+2], a[i*4+3]);
            }
#pragma unroll
            for (int i = 0; i < 4; i++)
#pragma unroll
                for (int j = 0; j < 8; j++) {
                    mma16816(acc[i][j], a[i*4], a[i*4+1], a[i*4+2], a[i*4+3], bh[2*j], bh[2*j+1]);
                    mma16816(acc[i][j], a[i*4], a[i*4+1], a[i*4+2], a[i*4+3], bl[2*j], bl[2*j+1]);
                }
#pragma unroll
            for (int i = 0; i < 4; i++) {
                const uint32_t ca = (uint32_t)(((kk * 2) + lac) ^ swA[i]) << 4;
                ldsm4(sb + 8192 + offA[i] + ca, a[i*4], a[i*4+1], a[i*4+2], a[i*4+3]);
            }
#pragma unroll
            for (int i = 0; i < 4; i++)
#pragma unroll
                for (int j = 0; j < 8; j++)
                    mma16816(acc[i][j], a[i*4], a[i*4+1], a[i*4+2], a[i*4+3], bh[2*j], bh[2*j+1]);
        }
        if (++st == 3) st = 0;
    }

    const int rr = lane >> 2, cc = (lane & 3) * 2;
#pragma unroll
    for (int i = 0; i < 4; i++) {
        const int row = m0 + wm + i * 16 + rr;
#pragma unroll
        for (int j = 0; j < 8; j++) {
            const int col = n0 + wn + j * 8 + cc;
            if (OUT == 0) {
                float* Cz = C + (long)z * sC;
                *(float2*)&Cz[(long)row * ldc + col]       = make_float2(acc[i][j][0], acc[i][j][1]);
                *(float2*)&Cz[(long)(row + 8) * ldc + col] = make_float2(acc[i][j][2], acc[i][j][3]);
            } else {
                bf16* Chz = Ch + (long)z * sC;
                bf16* Clz = Cl + (long)z * sC;
                bf16 h0, h1, l0, l1;
                split2(acc[i][j][0], h0, l0); split2(acc[i][j][1], h1, l1);
                *(__nv_bfloat162*)&Chz[(long)row * ldc + col] = __halves2bfloat162(h0, h1);
                *(__nv_bfloat162*)&Clz[(long)row * ldc + col] = __halves2bfloat162(l0, l1);
                split2(acc[i][j][2], h0, l0); split2(acc[i][j][3], h1, l1);
                *(__nv_bfloat162*)&Chz[(long)(row + 8) * ldc + col] = __halves2bfloat162(h0, h1);
                *(__nv_bfloat162*)&Clz[(long)(row + 8) * ldc + col] = __halves2bfloat162(l0, l1);
            }
        }
    }
}

// ---------------------------------------------------------------------------
// Fused softmax+PV: C_z[2048 rows][128] = softmax(masked Sc_z) @ V_z
// Same mainloop as mma_nt; A tiles produced in-kernel: exp((masked s) - M)
// split to bf16 hi/lo into smem; epilogue scales by 1/L, writes split bf16.
// B = Vt_z [128][2048] via cp.async.  grid (1, 16, NZ).
// ---------------------------------------------------------------------------
__global__ void __launch_bounds__(128)
pv_nt(const float* __restrict__ Sc, const int* __restrict__ msk,
      const float* __restrict__ Mrow, const float* __restrict__ Lrow,
      const bf16* __restrict__ Bh, const bf16* __restrict__ Bl,
      bf16* __restrict__ Ch, bf16* __restrict__ Cl)
{
    extern __shared__ char smem[];
    const uint32_t sbase = (uint32_t)__cvta_generic_to_shared(smem);
    int*   smk = (int*)  (smem + 98304);
    int*   smq = (int*)  (smem + 98304 + 8192);
    float* smm = (float*)(smem + 98304 + 8192 + 512);

    const int z  = blockIdx.z;
    const int b  = z >> 4;
    const int m0 = blockIdx.y * 128;
    const float* A = Sc + (long)z * Ss * Ss;
    Bh += (long)z * ((long)HDim * Ss);
    Bl += (long)z * ((long)HDim * Ss);

    const int tid  = threadIdx.x;
    const int lane = tid & 31;
    const int w    = tid >> 5;
    const int wm   = (w & 2) * 32;
    const int wn   = (w & 1) * 64;

    // prologue tables
    for (int i = tid; i < Ss / 4; i += 128)
        ((int4*)smk)[i] = ((const int4*)(msk + (long)b * Ss))[i];
    smq[tid] = msk[(long)b * Ss + m0 + tid];
    smm[tid] = Mrow[(long)z * Ss + m0 + tid];
    __syncthreads();

    const int la15 = lane & 15;
    const int lac  = lane >> 4;
    const int lb   = ((lane >> 4) << 3) + (lane & 7);
    const int lbg  = (lane >> 3) & 1;

    int offA[4], swA[4];
#pragma unroll
    for (int i = 0; i < 4; i++) {
        int r = wm + i * 16 + la15;
        offA[i] = r * 64;  swA[i] = (r >> 1) & 3;
    }
    int offB[4], swB[4];
#pragma unroll
    for (int p = 0; p < 4; p++) {
        int r = wn + p * 16 + lb;
        offB[p] = r * 64;  swB[p] = (r >> 1) & 3;
    }

    float acc[4][8][4];
#pragma unroll
    for (int i = 0; i < 4; i++)
#pragma unroll
        for (int j = 0; j < 8; j++)
#pragma unroll
            for (int r = 0; r < 4; r++) acc[i][j][r] = 0.0f;

    auto load_stage = [&](int t, int st) {
        const uint32_t sb = sbase + st * 32768;
        const int k0 = t * 32;
        // B tiles (Vt hi/lo) via cp.async: 128 rows x 32 cols each
#pragma unroll
        for (int i = 0; i < 8; i++) {
            const int q = i * 128 + tid;     // 0..1023 over 2 tiles x 512
            const int tile = q >> 9;         // 0: Bh, 1: Bl
            const int idx = q & 511;
            const int row = idx >> 2, c = idx & 3;
            const uint32_t sw = row * 64 + ((c ^ ((row >> 1) & 3)) << 4);
            const bf16* g = (tile ? Bl : Bh) + (long)row * Ss + k0 + c * 8;
            cpa16(sb + 16384 + tile * 8192 + sw, g);
        }
        asm volatile("cp.async.commit_group;" ::: "memory");
        // A tiles: p = exp(masked(s) - m), split hi/lo, store swizzled
#pragma unroll
        for (int i = 0; i < 8; i++) {
            const int q = i * 128 + tid;     // 128 rows x 8 float4
            const int row = q >> 3, f4 = q & 7;
            const int k = k0 + f4 * 4;
            const float4 v = *(const float4*)(A + (long)(m0 + row) * Ss + k);
            const int   mqv  = smq[row];
            const float mr   = smm[row];
            const float s0 = (mqv == 0 || smk[k+0] == 0) ? -1000000.0f : v.x;
            const float s1 = (mqv == 0 || smk[k+1] == 0) ? -1000000.0f : v.y;
            const float s2 = (mqv == 0 || smk[k+2] == 0) ? -1000000.0f : v.z;
            const float s3 = (mqv == 0 || smk[k+3] == 0) ? -1000000.0f : v.w;
            const float p0 = __expf(s0 - mr);
            const float p1 = __expf(s1 - mr);
            const float p2 = __expf(s2 - mr);
            const float p3 = __expf(s3 - mr);
            bf16 h0,h1,h2,h3,l0,l1,l2,l3;
            split2(p0,h0,l0); split2(p1,h1,l1); split2(p2,h2,l2); split2(p3,h3,l3);
            const int c = f4 >> 1;
            const uint32_t sw = (uint32_t)(row * 64 + ((c ^ ((row >> 1) & 3)) << 4) + (f4 & 1) * 8);
            *(__nv_bfloat162*)(smem + st * 32768 + sw)            = __halves2bfloat162(h0, h1);
            *(__nv_bfloat162*)(smem + st * 32768 + sw + 4)        = __halves2bfloat162(h2, h3);
            *(__nv_bfloat162*)(smem + st * 32768 + 8192 + sw)     = __halves2bfloat162(l0, l1);
            *(__nv_bfloat162*)(smem + st * 32768 + 8192 + sw + 4) = __halves2bfloat162(l2, l3);
        }
    };

    const int T = Ss >> 5;   // 64
    load_stage(0, 0);
    load_stage(1, 1);

    int st = 0;
    for (int t = 0; t < T; t++) {
        if (t < T - 1) asm volatile("cp.async.wait_group 1;" ::: "memory");
        else           asm volatile("cp.async.wait_group 0;" ::: "memory");
        __syncthreads();
        if (t + 2 < T) {
            int ns = st + 2; if (ns >= 3) ns -= 3;
            load_stage(t + 2, ns);
        }

        const uint32_t sb = sbase + st * 32768;
#pragma unroll
        for (int kk = 0; kk < 2; kk++) {
            uint32_t bh[16], bl[16], a[16];
#pragma unroll
            for (int p = 0; p < 4; p++) {
                const uint32_t ca = (uint32_t)(((kk * 2) + lbg) ^ swB[p]) << 4;
                ldsm4(sb + 16384 + offB[p] + ca, bh[p*4], bh[p*4+1], bh[p*4+2], bh[p*4+3]);
                ldsm4(sb + 24576 + offB[p] + ca, bl[p*4], bl[p*4+1], bl[p*4+2], bl[p*4+3]);
            }
#pragma unroll
            for (int i = 0; i < 4; i++) {
                const uint32_t ca = (uint32_t)(((kk * 2) + lac) ^ swA[i]) << 4;
                ldsm4(sb + offA[i] + ca, a[i*4], a[i*4+1], a[i*4+2], a[i*4+3]);
            }
#pragma unroll
            for (int i = 0; i < 4; i++)
#pragma unroll
                for (int j = 0; j < 8; j++) {
                    mma16816(acc[i][j], a[i*4], a[i*4+1], a[i*4+2], a[i*4+3], bh[2*j], bh[2*j+1]);
                    mma16816(acc[i][j], a[i*4], a[i*4+1], a[i*4+2], a[i*4+3], bl[2*j], bl[2*j+1]);
                }
#pragma unroll
            for (int i = 0; i < 4; i++) {
                const uint32_t ca = (uint32_t)(((kk * 2) + lac) ^ swA[i]) << 4;
                ldsm4(sb + 8192 + offA[i] + ca, a[i*4], a[i*4+1], a[i*4+2], a[i*4+3]);
            }
#pragma unroll
            for (int i = 0; i < 4; i++)
#pragma unroll
                for (int j = 0; j < 8; j++)
                    mma16816(acc[i][j], a[i*4], a[i*4+1], a[i*4+2], a[i*4+3], bh[2*j], bh[2*j+1]);
        }
        if (++st == 3) st = 0;
    }

    // epilogue: scale by 1/L, split, write
    Ch += (long)z * ((long)Ss * HDim);
    Cl += (long)z * ((long)Ss * HDim);
    const int rr = lane >> 2, cc = (lane & 3) * 2;
#pragma unroll
    for (int i = 0; i < 4; i++) {
        const int row = m0 + wm + i * 16 + rr;
        const float inv0 = 1.0f / Lrow[(long)z * Ss + row];
        const float inv1 = 1.0f / Lrow[(long)z * Ss + row + 8];
#pragma unroll
        for (int j = 0; j < 8; j++) {
            const int col = wn + j * 8 + cc;
            bf16 h0, h1, l0, l1;
            split2(acc[i][j][0] * inv0, h0, l0); split2(acc[i][j][1] * inv0, h1, l1);
            *(__nv_bfloat162*)&Ch[(long)row * HDim + col] = __halves2bfloat162(h0, h1);
            *(__nv_bfloat162*)&Cl[(long)row * HDim + col] = __halves2bfloat162(l0, l1);
            split2(acc[i][j][2] * inv1, h0, l0); split2(acc[i][j][3] * inv1, h1, l1);
            *(__nv_bfloat162*)&Ch[(long)(row + 8) * HDim + col] = __halves2bfloat162(h0, h1);
            *(__nv_bfloat162*)&Cl[(long)(row + 8) * HDim + col] = __halves2bfloat162(l0, l1);
        }
    }
}

// ---------------------------------------------------------------------------
// per-row masked max and sum-of-exp (one block per score row)
// ---------------------------------------------------------------------------
__global__ void __launch_bounds__(256)
rowstats(const float* __restrict__ scores, const int* __restrict__ mask,
         float* __restrict__ Mo, float* __restrict__ Lo)
{
    const long r = blockIdx.x;
    const int  q = (int)(r & (Ss - 1));
    const int  z = (int)(r >> 11);
    const int  b = z >> 4;
    const float* row  = scores + r * (long)Ss;
    const int*   mrow = mask + b * Ss;
    const int    mq   = mrow[q];
    const int    tid  = threadIdx.x;

    __shared__ float red_m[8];
    __shared__ float red_s[8];

    float v[8];
    float mx = -3.0e38f;
#pragma unroll
    for (int i = 0; i < 8; i++) {
        const int k = tid + i * 256;
        float s = row[k];
        if (mq == 0 || mrow[k] == 0) s = -1000000.0f;
        v[i] = s;
        mx = fmaxf(mx, s);
    }
#pragma unroll
    for (int o = 16; o > 0; o >>= 1)
        mx = fmaxf(mx, __shfl_xor_sync(0xffffffffu, mx, o));
    if ((tid & 31) == 0) red_m[tid >> 5] = mx;
    __syncthreads();
    mx = red_m[0];
#pragma unroll
    for (int i = 1; i < 8; i++) mx = fmaxf(mx, red_m[i]);

    float sum = 0.0f;
#pragma unroll
    for (int i = 0; i < 8; i++)
        sum += __expf(v[i] - mx);
#pragma unroll
    for (int o = 16; o > 0; o >>= 1)
        sum += __shfl_xor_sync(0xffffffffu, sum, o);
    if ((tid & 31) == 0) red_s[tid >> 5] = sum;
    __syncthreads();
    if (tid == 0) {
        float tot = red_s[0];
#pragma unroll
        for (int i = 1; i < 8; i++) tot += red_s[i];
        Mo[r] = mx;
        Lo[r] = tot;
    }
}

// ---------------------------------------------------------------------------
// split fp32 -> (hi, lo) bf16, same layout
// ---------------------------------------------------------------------------
__global__ void __launch_bounds__(256)
split_plain(const float* __restrict__ in, bf16* __restrict__ oh,
            bf16* __restrict__ ol, long n4)
{
    long i = (long)blockIdx.x * blockDim.x + threadIdx.x;
    const long stride = (long)gridDim.x * blockDim.x;
    for (; i < n4; i += stride) {
        const float4 v = ((const float4*)in)[i];
        bf16 h0, h1, h2, h3, l0, l1, l2, l3;
        split2(v.x, h0, l0); split2(v.y, h1, l1);
        split2(v.z, h2, l2); split2(v.w, h3, l3);
        ((__nv_bfloat162*)oh)[i*2]   = __halves2bfloat162(h0, h1);
        ((__nv_bfloat162*)oh)[i*2+1] = __halves2bfloat162(h2, h3);
        ((__nv_bfloat162*)ol)[i*2]   = __halves2bfloat162(l0, l1);
        ((__nv_bfloat162*)ol)[i*2+1] = __halves2bfloat162(l2, l3);
    }
}

// ---------------------------------------------------------------------------
// split fp32 [R][C] -> transposed (hi, lo) bf16 [C][R]
// ---------------------------------------------------------------------------
__global__ void __launch_bounds__(256)
split_tr(const float* __restrict__ in, bf16* __restrict__ oh,
         bf16* __restrict__ ol, int R, int C)
{
    __shared__ float t[32][33];
    const int c0 = blockIdx.x * 32, r0 = blockIdx.y * 32;
    const int tx = threadIdx.x, ty = threadIdx.y;
#pragma unroll
    for (int i = 0; i < 4; i++)
        t[ty + i * 8][tx] = in[(long)(r0 + ty + i * 8) * C + c0 + tx];
    __syncthreads();
#pragma unroll
    for (int i = 0; i < 4; i++) {
        const float v = t[tx][ty + i * 8];
        bf16 h, l; split2(v, h, l);
        const long o = (long)(c0 + ty + i * 8) * R + r0 + tx;
        oh[o] = h; ol[o] = l;
    }
}

// ---------------------------------------------------------------------------
// bf16 pair transpose: [z][R][C] -> [z][C][R] for both h and l tensors
// ---------------------------------------------------------------------------
__global__ void __launch_bounds__(256)
tr2bf(const bf16* __restrict__ inh, const bf16* __restrict__ inl,
      bf16* __restrict__ outh, bf16* __restrict__ outl, int R, int C)
{
    __shared__ bf16 th[32][33];
    __shared__ bf16 tl[32][33];
    const long zo = (long)blockIdx.z * R * C;
    inh += zo; inl += zo; outh += zo; outl += zo;
    const int c0 = blockIdx.x * 32, r0 = blockIdx.y * 32;
    const int tx = threadIdx.x, ty = threadIdx.y;
#pragma unroll
    for (int i = 0; i < 4; i++) {
        const long o = (long)(r0 + ty + i * 8) * C + c0 + tx;
        th[ty + i * 8][tx] = inh[o];
        tl[ty + i * 8][tx] = inl[o];
    }
    __syncthreads();
#pragma unroll
    for (int i = 0; i < 4; i++) {
        const long o = (long)(c0 + ty + i * 8) * R + r0 + tx;
        outh[o] = th[tx][ty + i * 8];
        outl[o] = tl[tx][ty + i * 8];
    }
}

// ---------------------------------------------------------------------------
extern "C" void kernel_launch(void* const* d_in, const int* in_sizes, int n_in,
                              void* d_out, int out_size)
{
    (void)in_sizes; (void)n_in; (void)out_size;
    const float* X   = (const float*)d_in[0];
    const int*   msk = (const int*)  d_in[1];
    const float* Wq  = (const float*)d_in[2];
    const float* Wk  = (const float*)d_in[3];
    const float* Wv  = (const float*)d_in[4];
    const float* Wqm = (const float*)d_in[5];
    const float* Wkm = (const float*)d_in[6];
    const float* Wvm = (const float*)d_in[7];
    const float* Wo  = (const float*)d_in[8];
    float* Y = (float*)d_out;

    float *Sc, *Mv, *Lv;
    bf16 *tAh, *tAl, *tBh, *tBl, *WcTh, *WcTl, *Xh, *Xl;
    bf16 *Pjh, *Pjl, *Vth, *Vtl, *Atth, *Attl;
    cudaGetSymbolAddress((void**)&Sc,   g_Sc);
    cudaGetSymbolAddress((void**)&Mv,   g_M);
    cudaGetSymbolAddress((void**)&Lv,   g_L);
    cudaGetSymbolAddress((void**)&tAh,  g_tAh);  cudaGetSymbolAddress((void**)&tAl,  g_tAl);
    cudaGetSymbolAddress((void**)&tBh,  g_tBh);  cudaGetSymbolAddress((void**)&tBl,  g_tBl);
    cudaGetSymbolAddress((void**)&WcTh, g_WcTh); cudaGetSymbolAddress((void**)&WcTl, g_WcTl);
    cudaGetSymbolAddress((void**)&Xh,   g_Xh);   cudaGetSymbolAddress((void**)&Xl,   g_Xl);
    cudaGetSymbolAddress((void**)&Pjh,  g_Pjh);  cudaGetSymbolAddress((void**)&Pjl,  g_Pjl);
    cudaGetSymbolAddress((void**)&Vth,  g_Vth);  cudaGetSymbolAddress((void**)&Vtl,  g_Vtl);
    cudaGetSymbolAddress((void**)&Atth, g_Atth); cudaGetSymbolAddress((void**)&Attl, g_Attl);

    const unsigned SMB  = 98304;           // GEMM smem: 3 stages * 32KB
    const unsigned SMBP = 98304 + 8192 + 512 + 512;   // pv smem + tables
    cudaFuncSetAttribute(mma_nt<0>, cudaFuncAttributeMaxDynamicSharedMemorySize, SMB);
    cudaFuncSetAttribute(mma_nt<1>, cudaFuncAttributeMaxDynamicSharedMemorySize, SMB);
    cudaFuncSetAttribute(pv_nt,     cudaFuncAttributeMaxDynamicSharedMemorySize, SMBP);

    const dim3 b128(128);
    const dim3 b256(256);
    const dim3 bTr(32, 8);
    const dim3 gTrW(Hh / 32, Hh / 32, 1);
    const long W4 = 4194304;   // weight slice elems
    const long P8 = 8388608;   // projection slice elems

    // split X once
    split_plain<<<8192, b256>>>(X, Xh, Xl, P8 / 4);

    // per-s weight splits into slices
    const float* Wt[3]  = {Wq, Wk, Wv};
    const float* Wmt[3] = {Wqm, Wkm, Wvm};
    for (int s = 0; s < 3; s++) {
        split_plain<<<4096, b256>>>(Wt[s], tBh + s * W4, tBl + s * W4, W4 / 4);
        split_tr<<<gTrW, bTr>>>(Wmt[s], tAh + s * W4, tAl + s * W4, Hh, Hh);
    }

    // batched weight-combine: WcT_s = Wm_s^T @ W_s^T   (z = 3)
    mma_nt<1><<<dim3(16, 16, 3), b128, SMB>>>(
        tAh, tAl, tBh, tBl, nullptr, WcTh, WcTl,
        Hh, Hh, Hh, Hh, W4, W4, W4);

    // batched projections: P_s = X @ Wc_s (shared A, z = 3) -> Q|K|V split
    mma_nt<1><<<dim3(16, 32, 3), b128, SMB>>>(
        Xh, Xl, WcTh, WcTl, nullptr, Pjh, Pjl,
        Hh, Hh, Hh, Hh, 0, W4, P8);

    // per-head V^T (bf16 pair transpose of the V slice)
    tr2bf<<<dim3(HDim / 32, Ss / 32, NZ), bTr>>>(
        Pjh + 2 * P8, Pjl + 2 * P8, Vth, Vtl, Ss, HDim);

    // scores: Sc_z = Qh_z @ Kh_z^T
    mma_nt<0><<<dim3(16, 16, NZ), b128, SMB>>>(
        Pjh, Pjl, Pjh + P8, Pjl + P8, Sc, nullptr, nullptr,
        HDim, HDim, HDim, Ss,
        (long)Ss * HDim, (long)Ss * HDim, (long)Ss * Ss);

    // row stats (masked max + sumexp)
    rowstats<<<(unsigned)(NZ * Ss), b256>>>(Sc, msk, Mv, Lv);

    // fused softmax + PV -> Att split
    pv_nt<<<dim3(1, 16, NZ), b128, SMBP>>>(
        Sc, msk, Mv, Lv, Vth, Vtl, Atth, Attl);

    // final: Y = Att @ Wo via NT with B = Wo^T (reuse tA slice 0)
    split_tr<<<gTrW, bTr>>>(Wo, tAh, tAl, Hh, Hh);
    mma_nt<0><<<dim3(16, 32, 1), b128, SMB>>>(
        Atth, Attl, tAh, tAl, Y, nullptr, nullptr,
        Hh, Hh, Hh, Hh, 0, 0, 0);
}

// round 8
// speedup vs baseline: 1.2294x; 1.2294x over previous
#include <cuda_runtime.h>
#include <cuda_bf16.h>
#include <cstdint>

#define Ss   2048
#define Hh   2048
#define BS   4096
#define NZ   32          // B * NUM_HEADS
#define HDim 128

typedef __nv_bfloat16 bf16;

// ---------------- fp32 scratch ----------------
__device__ float g_Sc[134217728];     // scores (fp32)

// ---------------- bf16 hi/lo scratch ----------------
__device__ bf16 g_tAh[12582912], g_tAl[12582912];   // 3x W?m^T slices; slice0 reused for Wo^T
__device__ bf16 g_tBh[12582912], g_tBl[12582912];   // 3x Wq/Wk/Wv
__device__ bf16 g_WcTh[12582912], g_WcTl[12582912]; // 3x combined weight^T
__device__ bf16 g_Xh[8388608],  g_Xl[8388608];
__device__ bf16 g_Pjh[25165824], g_Pjl[25165824];   // Q|K|V projections split (3 x 8M)
__device__ bf16 g_Vth[8388608], g_Vtl[8388608];     // per-head V^T: [32][128][2048]
__device__ bf16 g_Ph[134217728], g_Pl[134217728];   // softmax probs split
__device__ bf16 g_Atth[8388608], g_Attl[8388608];

// ---------------------------------------------------------------------------
// helpers
// ---------------------------------------------------------------------------
__device__ __forceinline__ void ldsm4(uint32_t a, uint32_t &r0, uint32_t &r1,
                                      uint32_t &r2, uint32_t &r3) {
    asm volatile("ldmatrix.sync.aligned.m8n8.x4.shared.b16 {%0,%1,%2,%3}, [%4];"
                 : "=r"(r0), "=r"(r1), "=r"(r2), "=r"(r3) : "r"(a));
}
__device__ __forceinline__ void mma16816(float c[4], uint32_t a0, uint32_t a1,
                                         uint32_t a2, uint32_t a3,
                                         uint32_t b0, uint32_t b1) {
    asm volatile("mma.sync.aligned.m16n8k16.row.col.f32.bf16.bf16.f32 "
                 "{%0,%1,%2,%3}, {%4,%5,%6,%7}, {%8,%9}, {%0,%1,%2,%3};"
                 : "+f"(c[0]), "+f"(c[1]), "+f"(c[2]), "+f"(c[3])
                 : "r"(a0), "r"(a1), "r"(a2), "r"(a3), "r"(b0), "r"(b1));
}
__device__ __forceinline__ void cpa16(uint32_t s, const void* g) {
    asm volatile("cp.async.cg.shared.global [%0], [%1], 16;" :: "r"(s), "l"(g));
}
__device__ __forceinline__ void split2(float x, bf16 &h, bf16 &l) {
    h = __float2bfloat16(x);
    l = __float2bfloat16(x - __bfloat162float(h));
}

// ---------------------------------------------------------------------------
// bf16x3 NT GEMM: C[M][N] = (Ah+Al)[M][K] @ (Bh+Bl)[N][K]^T (fp32 accum)
// 128x128 CTA tile, BK=32, 128 threads (4 warps, 2x2), warp tile 64x64.
// 3-stage cp.async ring. OUT=0: fp32 C.  OUT=1: bf16 hi/lo pair.
// ---------------------------------------------------------------------------
template <int OUT>
__global__ void __launch_bounds__(128)
mma_nt(const bf16* __restrict__ Ah, const bf16* __restrict__ Al,
       const bf16* __restrict__ Bh, const bf16* __restrict__ Bl,
       float* __restrict__ C, bf16* __restrict__ Ch, bf16* __restrict__ Cl,
       int K, int lda, int ldb, int ldc,
       long sA, long sB, long sC)
{
    extern __shared__ char smem[];
    const uint32_t sbase = (uint32_t)__cvta_generic_to_shared(smem);

    const int z = blockIdx.z;
    Ah += (long)z * sA;  Al += (long)z * sA;
    Bh += (long)z * sB;  Bl += (long)z * sB;

    const int m0 = blockIdx.y * 128;
    const int n0 = blockIdx.x * 128;
    const int tid  = threadIdx.x;
    const int lane = tid & 31;
    const int w    = tid >> 5;
    const int wm   = (w & 2) * 32;
    const int wn   = (w & 1) * 64;

    const int la15 = lane & 15;
    const int lac  = lane >> 4;
    const int lb   = ((lane >> 4) << 3) + (lane & 7);
    const int lbg  = (lane >> 3) & 1;

    int offA[4], swA[4];
#pragma unroll
    for (int i = 0; i < 4; i++) {
        int r = wm + i * 16 + la15;
        offA[i] = r * 64;  swA[i] = (r >> 1) & 3;
    }
    int offB[4], swB[4];
#pragma unroll
    for (int p = 0; p < 4; p++) {
        int r = wn + p * 16 + lb;
        offB[p] = r * 64;  swB[p] = (r >> 1) & 3;
    }

    float acc[4][8][4];
#pragma unroll
    for (int i = 0; i < 4; i++)
#pragma unroll
        for (int j = 0; j < 8; j++)
#pragma unroll
            for (int r = 0; r < 4; r++) acc[i][j][r] = 0.0f;

    auto load_stage = [&](int t, int st) {
        const uint32_t sb = sbase + st * 32768;
        const int k0 = t * 32;
#pragma unroll
        for (int i = 0; i < 16; i++) {
            const int q = i * 128 + tid;
            const int tile = q >> 9;
            const int idx = q & 511;
            const int row = idx >> 2, c = idx & 3;
            const uint32_t sw = row * 64 + ((c ^ ((row >> 1) & 3)) << 4);
            const bf16* g;
            if (tile == 0)      g = Ah + (long)(m0 + row) * lda + k0 + c * 8;
            else if (tile == 1) g = Al + (long)(m0 + row) * lda + k0 + c * 8;
            else if (tile == 2) g = Bh + (long)(n0 + row) * ldb + k0 + c * 8;
            else                g = Bl + (long)(n0 + row) * ldb + k0 + c * 8;
            cpa16(sb + tile * 8192 + sw, g);
        }
        asm volatile("cp.async.commit_group;" ::: "memory");
    };

    const int T = K >> 5;
    load_stage(0, 0);
    load_stage(1, 1);

    int st = 0;
    for (int t = 0; t < T; t++) {
        if (t < T - 1) asm volatile("cp.async.wait_group 1;" ::: "memory");
        else           asm volatile("cp.async.wait_group 0;" ::: "memory");
        __syncthreads();
        if (t + 2 < T) {
            int ns = st + 2; if (ns >= 3) ns -= 3;
            load_stage(t + 2, ns);
        }

        const uint32_t sb = sbase + st * 32768;
#pragma unroll
        for (int kk = 0; kk < 2; kk++) {
            uint32_t bh[16], bl[16], a[16];
#pragma unroll
            for (int p = 0; p < 4; p++) {
                const uint32_t ca = (uint32_t)(((kk * 2) + lbg) ^ swB[p]) << 4;
                ldsm4(sb + 16384 + offB[p] + ca, bh[p*4], bh[p*4+1], bh[p*4+2], bh[p*4+3]);
                ldsm4(sb + 24576 + offB[p] + ca, bl[p*4], bl[p*4+1], bl[p*4+2], bl[p*4+3]);
            }
#pragma unroll
            for (int i = 0; i < 4; i++) {
                const uint32_t ca = (uint32_t)(((kk * 2) + lac) ^ swA[i]) << 4;
                ldsm4(sb + offA[i] + ca, a[i*4], a[i*4+1], a[i*4+2], a[i*4+3]);
            }
#pragma unroll
            for (int i = 0; i < 4; i++)
#pragma unroll
                for (int j = 0; j < 8; j++) {
                    mma16816(acc[i][j], a[i*4], a[i*4+1], a[i*4+2], a[i*4+3], bh[2*j], bh[2*j+1]);
                    mma16816(acc[i][j], a[i*4], a[i*4+1], a[i*4+2], a[i*4+3], bl[2*j], bl[2*j+1]);
                }
#pragma unroll
            for (int i = 0; i < 4; i++) {
                const uint32_t ca = (uint32_t)(((kk * 2) + lac) ^ swA[i]) << 4;
                ldsm4(sb + 8192 + offA[i] + ca, a[i*4], a[i*4+1], a[i*4+2], a[i*4+3]);
            }
#pragma unroll
            for (int i = 0; i < 4; i++)
#pragma unroll
                for (int j = 0; j < 8; j++)
                    mma16816(acc[i][j], a[i*4], a[i*4+1], a[i*4+2], a[i*4+3], bh[2*j], bh[2*j+1]);
        }
        if (++st == 3) st = 0;
    }

    const int rr = lane >> 2, cc = (lane & 3) * 2;
#pragma unroll
    for (int i = 0; i < 4; i++) {
        const int row = m0 + wm + i * 16 + rr;
#pragma unroll
        for (int j = 0; j < 8; j++) {
            const int col = n0 + wn + j * 8 + cc;
            if (OUT == 0) {
                float* Cz = C + (long)z * sC;
                *(float2*)&Cz[(long)row * ldc + col]       = make_float2(acc[i][j][0], acc[i][j][1]);
                *(float2*)&Cz[(long)(row + 8) * ldc + col] = make_float2(acc[i][j][2], acc[i][j][3]);
            } else {
                bf16* Chz = Ch + (long)z * sC;
                bf16* Clz = Cl + (long)z * sC;
                bf16 h0, h1, l0, l1;
                split2(acc[i][j][0], h0, l0); split2(acc[i][j][1], h1, l1);
                *(__nv_bfloat162*)&Chz[(long)row * ldc + col] = __halves2bfloat162(h0, h1);
                *(__nv_bfloat162*)&Clz[(long)row * ldc + col] = __halves2bfloat162(l0, l1);
                split2(acc[i][j][2], h0, l0); split2(acc[i][j][3], h1, l1);
                *(__nv_bfloat162*)&Chz[(long)(row + 8) * ldc + col] = __halves2bfloat162(h0, h1);
                *(__nv_bfloat162*)&Clz[(long)(row + 8) * ldc + col] = __halves2bfloat162(l0, l1);
            }
        }
    }
}

// ---------------------------------------------------------------------------
// masked softmax over score rows; writes split bf16 probabilities
// ---------------------------------------------------------------------------
__global__ void __launch_bounds__(256)
masked_softmax_split(const float* __restrict__ scores, const int* __restrict__ mask,
                     bf16* __restrict__ ph, bf16* __restrict__ pl)
{
    const long r = blockIdx.x;
    const int  q = (int)(r & (Ss - 1));
    const int  z = (int)(r >> 11);
    const int  b = z >> 4;
    const float* row  = scores + r * (long)Ss;
    const int*   mrow = mask + b * Ss;
    const int    mq   = mrow[q];
    const int    tid  = threadIdx.x;

    __shared__ float red_m[8];
    __shared__ float red_s[8];

    float v[8];
    float mx = -3.0e38f;
#pragma unroll
    for (int i = 0; i < 8; i++) {
        const int k = tid + i * 256;
        float s = row[k];
        if (mq == 0 || mrow[k] == 0) s = -1000000.0f;
        v[i] = s;
        mx = fmaxf(mx, s);
    }
#pragma unroll
    for (int o = 16; o > 0; o >>= 1)
        mx = fmaxf(mx, __shfl_xor_sync(0xffffffffu, mx, o));
    if ((tid & 31) == 0) red_m[tid >> 5] = mx;
    __syncthreads();
    mx = red_m[0];
#pragma unroll
    for (int i = 1; i < 8; i++) mx = fmaxf(mx, red_m[i]);

    float sum = 0.0f;
#pragma unroll
    for (int i = 0; i < 8; i++) {
        v[i] = __expf(v[i] - mx);
        sum += v[i];
    }
#pragma unroll
    for (int o = 16; o > 0; o >>= 1)
        sum += __shfl_xor_sync(0xffffffffu, sum, o);
    if ((tid & 31) == 0) red_s[tid >> 5] = sum;
    __syncthreads();
    float tot = red_s[0];
#pragma unroll
    for (int i = 1; i < 8; i++) tot += red_s[i];

    const float inv = 1.0f / tot;
#pragma unroll
    for (int i = 0; i < 8; i++) {
        const float p = v[i] * inv;
        bf16 h, l; split2(p, h, l);
        const long o = r * (long)Ss + tid + i * 256;
        ph[o] = h; pl[o] = l;
    }
}

// ---------------------------------------------------------------------------
// split fp32 -> (hi, lo) bf16, same layout
// ---------------------------------------------------------------------------
__global__ void __launch_bounds__(256)
split_plain(const float* __restrict__ in, bf16* __restrict__ oh,
            bf16* __restrict__ ol, long n4)
{
    long i = (long)blockIdx.x * blockDim.x + threadIdx.x;
    const long stride = (long)gridDim.x * blockDim.x;
    for (; i < n4; i += stride) {
        const float4 v = ((const float4*)in)[i];
        bf16 h0, h1, h2, h3, l0, l1, l2, l3;
        split2(v.x, h0, l0); split2(v.y, h1, l1);
        split2(v.z, h2, l2); split2(v.w, h3, l3);
        ((__nv_bfloat162*)oh)[i*2]   = __halves2bfloat162(h0, h1);
        ((__nv_bfloat162*)oh)[i*2+1] = __halves2bfloat162(h2, h3);
        ((__nv_bfloat162*)ol)[i*2]   = __halves2bfloat162(l0, l1);
        ((__nv_bfloat162*)ol)[i*2+1] = __halves2bfloat162(l2, l3);
    }
}

// ---------------------------------------------------------------------------
// split fp32 [R][C] -> transposed (hi, lo) bf16 [C][R]
// ---------------------------------------------------------------------------
__global__ void __launch_bounds__(256)
split_tr(const float* __restrict__ in, bf16* __restrict__ oh,
         bf16* __restrict__ ol, int R, int C)
{
    __shared__ float t[32][33];
    const int c0 = blockIdx.x * 32, r0 = blockIdx.y * 32;
    const int tx = threadIdx.x, ty = threadIdx.y;
#pragma unroll
    for (int i = 0; i < 4; i++)
        t[ty + i * 8][tx] = in[(long)(r0 + ty + i * 8) * C + c0 + tx];
    __syncthreads();
#pragma unroll
    for (int i = 0; i < 4; i++) {
        const float v = t[tx][ty + i * 8];
        bf16 h, l; split2(v, h, l);
        const long o = (long)(c0 + ty + i * 8) * R + r0 + tx;
        oh[o] = h; ol[o] = l;
    }
}

// ---------------------------------------------------------------------------
// bf16 pair transpose: [z][R][C] -> [z][C][R] for both h and l tensors
// ---------------------------------------------------------------------------
__global__ void __launch_bounds__(256)
tr2bf(const bf16* __restrict__ inh, const bf16* __restrict__ inl,
      bf16* __restrict__ outh, bf16* __restrict__ outl, int R, int C)
{
    __shared__ bf16 th[32][33];
    __shared__ bf16 tl[32][33];
    const long zo = (long)blockIdx.z * R * C;
    inh += zo; inl += zo; outh += zo; outl += zo;
    const int c0 = blockIdx.x * 32, r0 = blockIdx.y * 32;
    const int tx = threadIdx.x, ty = threadIdx.y;
#pragma unroll
    for (int i = 0; i < 4; i++) {
        const long o = (long)(r0 + ty + i * 8) * C + c0 + tx;
        th[ty + i * 8][tx] = inh[o];
        tl[ty + i * 8][tx] = inl[o];
    }
    __syncthreads();
#pragma unroll
    for (int i = 0; i < 4; i++) {
        const long o = (long)(c0 + ty + i * 8) * R + r0 + tx;
        outh[o] = th[tx][ty + i * 8];
        outl[o] = tl[tx][ty + i * 8];
    }
}

// ---------------------------------------------------------------------------
extern "C" void kernel_launch(void* const* d_in, const int* in_sizes, int n_in,
                              void* d_out, int out_size)
{
    (void)in_sizes; (void)n_in; (void)out_size;
    const float* X   = (const float*)d_in[0];
    const int*   msk = (const int*)  d_in[1];
    const float* Wq  = (const float*)d_in[2];
    const float* Wk  = (const float*)d_in[3];
    const float* Wv  = (const float*)d_in[4];
    const float* Wqm = (const float*)d_in[5];
    const float* Wkm = (const float*)d_in[6];
    const float* Wvm = (const float*)d_in[7];
    const float* Wo  = (const float*)d_in[8];
    float* Y = (float*)d_out;

    float *Sc;
    bf16 *tAh, *tAl, *tBh, *tBl, *WcTh, *WcTl, *Xh, *Xl;
    bf16 *Pjh, *Pjl, *Vth, *Vtl, *Ph, *Pl, *Atth, *Attl;
    cudaGetSymbolAddress((void**)&Sc,   g_Sc);
    cudaGetSymbolAddress((void**)&tAh,  g_tAh);  cudaGetSymbolAddress((void**)&tAl,  g_tAl);
    cudaGetSymbolAddress((void**)&tBh,  g_tBh);  cudaGetSymbolAddress((void**)&tBl,  g_tBl);
    cudaGetSymbolAddress((void**)&WcTh, g_WcTh); cudaGetSymbolAddress((void**)&WcTl, g_WcTl);
    cudaGetSymbolAddress((void**)&Xh,   g_Xh);   cudaGetSymbolAddress((void**)&Xl,   g_Xl);
    cudaGetSymbolAddress((void**)&Pjh,  g_Pjh);  cudaGetSymbolAddress((void**)&Pjl,  g_Pjl);
    cudaGetSymbolAddress((void**)&Vth,  g_Vth);  cudaGetSymbolAddress((void**)&Vtl,  g_Vtl);
    cudaGetSymbolAddress((void**)&Ph,   g_Ph);   cudaGetSymbolAddress((void**)&Pl,   g_Pl);
    cudaGetSymbolAddress((void**)&Atth, g_Atth); cudaGetSymbolAddress((void**)&Attl, g_Attl);

    const unsigned SMB = 98304;   // 3 stages * 32KB
    cudaFuncSetAttribute(mma_nt<0>, cudaFuncAttributeMaxDynamicSharedMemorySize, SMB);
    cudaFuncSetAttribute(mma_nt<1>, cudaFuncAttributeMaxDynamicSharedMemorySize, SMB);

    const dim3 b128(128);
    const dim3 b256(256);
    const dim3 bTr(32, 8);
    const dim3 gTrW(Hh / 32, Hh / 32, 1);
    const long W4 = 4194304;   // weight slice elems
    const long P8 = 8388608;   // projection slice elems

    // split X once
    split_plain<<<8192, b256>>>(X, Xh, Xl, P8 / 4);

    // per-s weight splits into slices
    const float* Wt[3]  = {Wq, Wk, Wv};
    const float* Wmt[3] = {Wqm, Wkm, Wvm};
    for (int s = 0; s < 3; s++) {
        split_plain<<<4096, b256>>>(Wt[s], tBh + s * W4, tBl + s * W4, W4 / 4);
        split_tr<<<gTrW, bTr>>>(Wmt[s], tAh + s * W4, tAl + s * W4, Hh, Hh);
    }

    // batched weight-combine: WcT_s = Wm_s^T @ W_s^T   (z = 3)
    mma_nt<1><<<dim3(16, 16, 3), b128, SMB>>>(
        tAh, tAl, tBh, tBl, nullptr, WcTh, WcTl,
        Hh, Hh, Hh, Hh, W4, W4, W4);

    // batched projections: P_s = X @ Wc_s (shared A, z = 3) -> Q|K|V split
    mma_nt<1><<<dim3(16, 32, 3), b128, SMB>>>(
        Xh, Xl, WcTh, WcTl, nullptr, Pjh, Pjl,
        Hh, Hh, Hh, Hh, 0, W4, P8);

    // per-head V^T (bf16 pair transpose of the V slice)
    tr2bf<<<dim3(HDim / 32, Ss / 32, NZ), bTr>>>(
        Pjh + 2 * P8, Pjl + 2 * P8, Vth, Vtl, Ss, HDim);

    // scores: Sc_z = Qh_z @ Kh_z^T
    mma_nt<0><<<dim3(16, 16, NZ), b128, SMB>>>(
        Pjh, Pjl, Pjh + P8, Pjl + P8, Sc, nullptr, nullptr,
        HDim, HDim, HDim, Ss,
        (long)Ss * HDim, (long)Ss * HDim, (long)Ss * Ss);

    // masked softmax + split
    masked_softmax_split<<<(unsigned)(NZ * Ss), b256>>>(Sc, msk, Ph, Pl);

    // PV: Att_z = P_z @ V_z via NT with B = V_z^T, split-out epilogue
    mma_nt<1><<<dim3(1, 16, NZ), b128, SMB>>>(
        Ph, Pl, Vth, Vtl, nullptr, Atth, Attl,
        Ss, Ss, Ss, HDim,
        (long)Ss * Ss, (long)HDim * Ss, (long)Ss * HDim);

    // final: Y = Att @ Wo via NT with B = Wo^T (reuse tA slice 0)
    split_tr<<<gTrW, bTr>>>(Wo, tAh, tAl, Hh, Hh);
    mma_nt<0><<<dim3(16, 32, 1), b128, SMB>>>(
        Atth, Attl, tAh, tAl, Y, nullptr, nullptr,
        Hh, Hh, Hh, Hh, 0, 0, 0);
}